// round 15
// baseline (speedup 1.0000x reference)
#include <cuda_runtime.h>
#include <cuda_fp16.h>
#include <math.h>
#include <stdint.h>

#define NROWS 16384      // 2 * 8*32*32
#define NCODE 4096
#define KDIM  256
#define SPB   8192       // spatial per batch
#define ZTOT  4194304    // 2*256*8192

// output layout: concatenation of reference outputs, float32
#define OFF_LOSS   0ull
#define OFF_ZQ     1ull
#define OFF_PERP   4194305ull
#define OFF_OH     4194306ull
#define OFF_IDX    71303170ull
#define OFF_ZOUT   71319554ull
#define OFF_EMA    75513858ull

// B operand pre-scale for HMMA path: 2^12 (exact). Descale folded as 2^-11.
#define BSCALE 4096.0f

// ---------------- scratch ----------------
__device__ float  g_Anorm[NROWS];
__device__ float  g_Snorm[NCODE];
__device__ float  g_pd[NROWS * 32];
__device__ int    g_pj[NROWS * 32];
__device__ int    g_idx[NROWS];
__device__ int    g_cnt[NCODE];
__device__ double g_losspart[4096];
__device__ __align__(16) float g_Et[(size_t)KDIM * NCODE];   // E transposed [k][j], unscaled

// fp16-split operands packed in mma.m16n8k16 fragment order (half2 per reg).
__device__ __align__(16) uint32_t g_Afh[(size_t)1024 * 16 * 32 * 4];
__device__ __align__(16) uint32_t g_Afl[(size_t)1024 * 16 * 32 * 4];
__device__ __align__(16) uint32_t g_Bfh[(size_t)512 * 16 * 32 * 2];
__device__ __align__(16) uint32_t g_Bfl[(size_t)512 * 16 * 32 * 2];

// ---------------- helpers ----------------
__device__ __forceinline__ uint32_t smem_u32(const void* p) {
    uint32_t a;
    asm("{ .reg .u64 t; cvta.to.shared.u64 t, %1; cvt.u32.u64 %0, t; }" : "=r"(a) : "l"(p));
    return a;
}
#define CP_ASYNC16(dst, src) \
    asm volatile("cp.async.cg.shared.global [%0], [%1], 16;" :: "r"(dst), "l"(src) : "memory")
#define CP_COMMIT() asm volatile("cp.async.commit_group;" ::: "memory")
#define CP_WAIT0()  asm volatile("cp.async.wait_group 0;" ::: "memory")

__device__ __forceinline__ void mma_f16(float* c, const uint32_t* a, const uint32_t* b) {
    asm volatile("mma.sync.aligned.m16n8k16.row.col.f32.f16.f16.f32 "
        "{%0,%1,%2,%3}, {%4,%5,%6,%7}, {%8,%9}, {%0,%1,%2,%3};"
        : "+f"(c[0]), "+f"(c[1]), "+f"(c[2]), "+f"(c[3])
        : "r"(a[0]), "r"(a[1]), "r"(a[2]), "r"(a[3]), "r"(b[0]), "r"(b[1]));
}
// non-volatile: ptxas may schedule these into mma dispatch bubbles
__device__ __forceinline__ void ffma2(unsigned long long& acc, unsigned long long a,
                                      unsigned long long b) {
    asm("fma.rn.f32x2 %0, %1, %2, %0;" : "+l"(acc) : "l"(a), "l"(b));
}
__device__ __forceinline__ unsigned long long dup2(float x) {
    unsigned long long r;
    asm("mov.b64 %0, {%1, %1};" : "=l"(r) : "f"(x));
    return r;
}
__device__ __forceinline__ void unpack2(unsigned long long v, float& lo, float& hi) {
    asm("mov.b64 {%0, %1}, %2;" : "=f"(lo), "=f"(hi) : "l"(v));
}
__device__ __forceinline__ uint32_t pack_hi2(float x, float y, float& rx, float& ry) {
    __half hx = __float2half_rn(x), hy = __float2half_rn(y);
    rx = __fsub_rn(x, __half2float(hx));
    ry = __fsub_rn(y, __half2float(hy));
    __half2 h = __halves2half2(hx, hy);
    return *(uint32_t*)&h;
}
__device__ __forceinline__ void split2(float x, float y, uint32_t& hi, uint32_t& lo) {
    float rx, ry;
    hi = pack_hi2(x, y, rx, ry);
    __half2 l = __halves2half2(__float2half_rn(rx), __float2half_rn(ry));
    lo = *(uint32_t*)&l;
}

// ---------------------------------------------------------------- init
__global__ void k_init() {
    int t = blockIdx.x * 256 + threadIdx.x;
    if (t < NCODE) g_cnt[t] = 0;
}

// ---------------------------------------------------------------- row norms ||z_n||^2
__global__ void k_rownorm(const float* __restrict__ z) {
    int n = blockIdx.x * 256 + threadIdx.x;
    int b = n >> 13, s = n & (SPB - 1);
    const float* p = z + (size_t)b * (KDIM * SPB) + s;
    float a = 0.f;
    #pragma unroll 8
    for (int c = 0; c < KDIM; c++) {
        float v = p[(size_t)c * SPB];
        a = __fmaf_rn(v, v, a);
    }
    g_Anorm[n] = a;
}

// ---------------------------------------------------------------- code norms ||e_j||^2
__global__ void k_codenorm(const float* __restrict__ E) {
    int w = blockIdx.x * 8 + (threadIdx.x >> 5);
    int lane = threadIdx.x & 31;
    const float* p = E + (size_t)w * KDIM;
    float a = 0.f;
    #pragma unroll
    for (int i = 0; i < 8; i++) {
        float v = p[lane + i * 32];
        a = __fmaf_rn(v, v, a);
    }
    #pragma unroll
    for (int off = 16; off > 0; off >>= 1)
        a += __shfl_xor_sync(0xffffffffu, a, off);
    if (lane == 0) g_Snorm[w] = a;
}

// ---------------------------------------------------------------- E transpose: [j][k] -> [k][j] (unscaled)
__global__ void k_transposeE(const float* __restrict__ E) {
    __shared__ float tile[32][33];
    int tx = threadIdx.x, ty = threadIdx.y;   // 32 x 8
    int j0 = blockIdx.x * 32, k0 = blockIdx.y * 32;
    #pragma unroll
    for (int r = 0; r < 4; r++)
        tile[ty + r * 8][tx] = E[(size_t)(j0 + ty + r * 8) * KDIM + k0 + tx];
    __syncthreads();
    #pragma unroll
    for (int r = 0; r < 4; r++)
        g_Et[(size_t)(k0 + ty + r * 8) * NCODE + j0 + tx] = tile[tx][ty + r * 8];
}

// ---------------------------------------------------------------- A fragment pack
__global__ void k_packA(const float* __restrict__ z) {
    int tid = blockIdx.x * 256 + threadIdx.x;   // 524,288
    int l  = tid & 31;
    int kc = (tid >> 5) & 15;
    int T  = tid >> 9;                           // 0..1023
    int g = l >> 2, tg = l & 3;
    int m = T * 16;
    int b = m >> 13;
    int s = (m & (SPB - 1)) + g;
    int k0 = kc * 16 + tg * 2;
    const float* zb = z + ((size_t)b * KDIM * SPB);
    uint4 hi, lo;
    split2(zb[(size_t)k0 * SPB + s],           zb[(size_t)(k0 + 1) * SPB + s],       hi.x, lo.x);
    split2(zb[(size_t)k0 * SPB + s + 8],       zb[(size_t)(k0 + 1) * SPB + s + 8],   hi.y, lo.y);
    split2(zb[(size_t)(k0 + 8) * SPB + s],     zb[(size_t)(k0 + 9) * SPB + s],       hi.z, lo.z);
    split2(zb[(size_t)(k0 + 8) * SPB + s + 8], zb[(size_t)(k0 + 9) * SPB + s + 8],   hi.w, lo.w);
    size_t o = ((size_t)T * 16 + kc) * 128 + l * 4;
    *(uint4*)&g_Afh[o] = hi;
    *(uint4*)&g_Afl[o] = lo;
}

// ---------------------------------------------------------------- B fragment pack (scaled by BSCALE)
__global__ void k_packB(const float* __restrict__ E) {
    int tid = blockIdx.x * 256 + threadIdx.x;   // 262,144
    int l  = tid & 31;
    int kc = (tid >> 5) & 15;
    int nt = tid >> 9;                           // 0..511
    int g = l >> 2, tg = l & 3;
    int n = nt * 8 + g;
    int k0 = kc * 16 + tg * 2;
    uint32_t h0, l0, h1, l1;
    split2(E[(size_t)n * KDIM + k0] * BSCALE,     E[(size_t)n * KDIM + k0 + 1] * BSCALE, h0, l0);
    split2(E[(size_t)n * KDIM + k0 + 8] * BSCALE, E[(size_t)n * KDIM + k0 + 9] * BSCALE, h1, l1);
    size_t o = ((size_t)nt * 16 + kc) * 64 + l * 2;
    g_Bfh[o]     = h0;
    g_Bfh[o + 1] = h1;
    g_Bfl[o]     = l0;
    g_Bfl[o + 1] = l1;
}

// ---------------------------------------------------------------- hybrid GEMM + argmin
// block tile 128m x 128j; cols [0,96) HMMA 3-pass, cols [96,128) FFMA2 f32.
// stage = k32, double buffered.
#define SO_AH 0
#define SO_AL 8192
#define SO_BH 16384
#define SO_BL 22528
#define SO_AF 28672
#define SO_BF 45056
#define STG   49152
#define SM_RED  (512 + 2 * STG)
#define SM_REDJ (SM_RED + 4096)
#define GSMEM   (SM_REDJ + 4096)

__device__ __forceinline__ void copy_stage(char* sm_, int st, int ks, int bm, int bn, int t,
                                           const float* zb, int s0) {
    uint32_t sb = smem_u32(sm_ + 512 + st * STG);
    const int k0g = ks * 32;
    // A fragments hi+lo: 1024 chunks of 16B
    #pragma unroll
    for (int i = 0; i < 4; i++) {
        int a = t + i * 256;
        int half = a >> 9, c = a & 511;
        int kc = c >> 8, mt = (c >> 5) & 7, lane = c & 31;
        const uint32_t* src = (half ? g_Afl : g_Afh)
            + (((size_t)(bm * 8 + mt) * 16 + ks * 2 + kc) * 32 + lane) * 4;
        CP_ASYNC16(sb + (half ? SO_AL : SO_AH) + c * 16, src);
    }
    // B fragments hi+lo for 12 ntiles: 768 chunks
    #pragma unroll
    for (int i = 0; i < 3; i++) {
        int a = t + i * 256;                  // 0..767
        int half = a >= 384;
        int c = half ? a - 384 : a;           // 0..383
        int e = c * 2;
        int nt = e >> 6;
        int rem = e & 63;
        int kc = rem >> 5, lane = rem & 31;
        const uint32_t* src = (half ? g_Bfl : g_Bfh)
            + (((size_t)(bn * 16 + nt) * 16 + ks * 2 + kc) * 32 + lane) * 2;
        CP_ASYNC16(sb + (half ? SO_BL : SO_BH) + c * 16, src);
    }
    // A f32 [k][128] straight from z: 1024 chunks
    #pragma unroll
    for (int i = 0; i < 4; i++) {
        int c = t + i * 256;
        int k = c >> 5, mo = (c & 31) * 4;
        CP_ASYNC16(sb + SO_AF + (uint32_t)(k * 128 + mo) * 4,
                   zb + (size_t)(k0g + k) * SPB + s0 + mo);
    }
    // B f32 [k][32] from E^T (cols j0+96..j0+127): 256 chunks
    {
        int c = t;
        int k = c >> 3, jo = (c & 7) * 4;
        CP_ASYNC16(sb + SO_BF + (uint32_t)(k * 32 + jo) * 4,
                   g_Et + (size_t)(k0g + k) * NCODE + bn * 128 + 96 + jo);
    }
}

__global__ __launch_bounds__(256, 1)
void k_gemm_hybrid(const float* __restrict__ z) {
    extern __shared__ char sm_[];
    const int t = threadIdx.x, lane = t & 31, wid = t >> 5;
    const int wm = wid >> 2;         // 0..1  (m offset wm*64)
    const int wn = wid & 3;          // 0..3  (hmma col group: cols wn*24..wn*24+23)
    const int g = lane >> 2, tg = lane & 3;
    const int rp = t & 63;           // ffma2 row-pair (rows 2rp, 2rp+1)
    const int cg = t >> 6;           // ffma2 col group (cols 96+cg*8 .. +7)
    const int bn = blockIdx.x, bm = blockIdx.y;
    const int n0 = bm * 128, j0 = bn * 128;
    const int b = n0 >> 13, s0 = n0 & (SPB - 1);
    const float* zb = z + (size_t)b * (KDIM * SPB);

    float* sSn  = (float*)sm_;
    float* redD = (float*)(sm_ + SM_RED);
    int*   redJ = (int*)(sm_ + SM_REDJ);

    if (t < 128) sSn[t] = g_Snorm[j0 + t];

    copy_stage(sm_, 0, 0, bm, bn, t, zb, s0);
    CP_COMMIT();

    float acc[4][3][4];
    #pragma unroll
    for (int a = 0; a < 4; a++)
        #pragma unroll
        for (int bb = 0; bb < 3; bb++)
            #pragma unroll
            for (int c = 0; c < 4; c++) acc[a][bb][c] = 0.f;
    unsigned long long facc[8];
    #pragma unroll
    for (int c = 0; c < 8; c++) facc[c] = 0ull;

    for (int ks = 0; ks < 8; ks++) {
        CP_WAIT0();
        __syncthreads();
        if (ks + 1 < 8) {
            copy_stage(sm_, (ks + 1) & 1, ks + 1, bm, bn, t, zb, s0);
            CP_COMMIT();
        }
        char* sbase = sm_ + 512 + (ks & 1) * STG;
        #pragma unroll
        for (int kc = 0; kc < 2; kc++) {
            uint32_t ah[4][4], al_[4][4], bh[3][2], bl[3][2];
            #pragma unroll
            for (int j = 0; j < 4; j++) {
                uint4 x = *(const uint4*)(sbase + SO_AH + ((kc * 8 + wm * 4 + j) * 32 + lane) * 16);
                ah[j][0] = x.x; ah[j][1] = x.y; ah[j][2] = x.z; ah[j][3] = x.w;
                uint4 y = *(const uint4*)(sbase + SO_AL + ((kc * 8 + wm * 4 + j) * 32 + lane) * 16);
                al_[j][0] = y.x; al_[j][1] = y.y; al_[j][2] = y.z; al_[j][3] = y.w;
            }
            #pragma unroll
            for (int j = 0; j < 3; j++) {
                int nt = wn * 3 + j;
                uint2 u = *(const uint2*)(sbase + SO_BH + ((nt * 2 + kc) * 32 + lane) * 8);
                bh[j][0] = u.x; bh[j][1] = u.y;
                uint2 v = *(const uint2*)(sbase + SO_BL + ((nt * 2 + kc) * 32 + lane) * 8);
                bl[j][0] = v.x; bl[j][1] = v.y;
            }
            // 3-pass HMMA (pass-major; per-acc order hh -> hl -> lh, bit-exact vs R12)
            #pragma unroll
            for (int mt = 0; mt < 4; mt++)
                #pragma unroll
                for (int nt = 0; nt < 3; nt++)
                    mma_f16(acc[mt][nt], ah[mt], bh[nt]);
            #pragma unroll
            for (int mt = 0; mt < 4; mt++)
                #pragma unroll
                for (int nt = 0; nt < 3; nt++)
                    mma_f16(acc[mt][nt], ah[mt], bl[nt]);
            #pragma unroll
            for (int mt = 0; mt < 4; mt++)
                #pragma unroll
                for (int nt = 0; nt < 3; nt++)
                    mma_f16(acc[mt][nt], al_[mt], bh[nt]);
            // FFMA2 cols (fills mma dispatch bubbles; k sequential -> R7 composition)
            #pragma unroll
            for (int kk = 0; kk < 16; kk++) {
                int k = kc * 16 + kk;
                unsigned long long av =
                    *(const unsigned long long*)(sbase + SO_AF + (uint32_t)(k * 128 + rp * 2) * 4);
                float4 b0 = *(const float4*)(sbase + SO_BF + (uint32_t)(k * 32 + cg * 8) * 4);
                float4 b1 = *(const float4*)(sbase + SO_BF + (uint32_t)(k * 32 + cg * 8 + 4) * 4);
                ffma2(facc[0], av, dup2(b0.x));
                ffma2(facc[1], av, dup2(b0.y));
                ffma2(facc[2], av, dup2(b0.z));
                ffma2(facc[3], av, dup2(b0.w));
                ffma2(facc[4], av, dup2(b1.x));
                ffma2(facc[5], av, dup2(b1.y));
                ffma2(facc[6], av, dup2(b1.z));
                ffma2(facc[7], av, dup2(b1.w));
            }
        }
    }
    __syncthreads();

    // ---- HMMA epilogue: d = fl( fl(An+Sj) - 2^-11 * acc ), cols [0,96) ----
    #pragma unroll
    for (int mt = 0; mt < 4; mt++) {
        int r0 = wm * 64 + mt * 16 + g;
        int r1 = r0 + 8;
        float an0 = g_Anorm[n0 + r0];
        float an1 = g_Anorm[n0 + r1];
        float bd0 = __int_as_float(0x7f800000), bd1 = bd0;
        int bj0 = 0, bj1 = 0;
        #pragma unroll
        for (int nt = 0; nt < 3; nt++) {
            #pragma unroll
            for (int e = 0; e < 2; e++) {
                int cl = wn * 24 + nt * 8 + tg * 2 + e;
                float sj = sSn[cl];
                int j = j0 + cl;
                float d0 = __fmaf_rn(-0x1p-11f, acc[mt][nt][e],     __fadd_rn(an0, sj));
                float d1 = __fmaf_rn(-0x1p-11f, acc[mt][nt][2 + e], __fadd_rn(an1, sj));
                if (d0 < bd0) { bd0 = d0; bj0 = j; }
                if (d1 < bd1) { bd1 = d1; bj1 = j; }
            }
        }
        #pragma unroll
        for (int off = 1; off <= 2; off <<= 1) {
            float d2 = __shfl_xor_sync(0xffffffffu, bd0, off);
            int   j2 = __shfl_xor_sync(0xffffffffu, bj0, off);
            if (d2 < bd0 || (d2 == bd0 && j2 < bj0)) { bd0 = d2; bj0 = j2; }
            float d3 = __shfl_xor_sync(0xffffffffu, bd1, off);
            int   j3 = __shfl_xor_sync(0xffffffffu, bj1, off);
            if (d3 < bd1 || (d3 == bd1 && j3 < bj1)) { bd1 = d3; bj1 = j3; }
        }
        if (tg == 0) {
            redD[r0 * 8 + wn] = bd0; redJ[r0 * 8 + wn] = bj0;
            redD[r1 * 8 + wn] = bd1; redJ[r1 * 8 + wn] = bj1;
        }
    }

    // ---- FFMA2 epilogue: d = fl( fl(An+Sj) - 2*acc ), cols [96,128) ----
    {
        int rlo = 2 * rp, rhi = 2 * rp + 1;
        float anl = g_Anorm[n0 + rlo];
        float anh = g_Anorm[n0 + rhi];
        float bdl = __int_as_float(0x7f800000), bdh = bdl;
        int bjl = 0, bjh = 0;
        #pragma unroll
        for (int c = 0; c < 8; c++) {
            float lo, hi;
            unpack2(facc[c], lo, hi);
            int cl = 96 + cg * 8 + c;
            float sj = sSn[cl];
            int j = j0 + cl;
            float dl = __fmaf_rn(-2.0f, lo, __fadd_rn(anl, sj));
            float dh = __fmaf_rn(-2.0f, hi, __fadd_rn(anh, sj));
            if (dl < bdl) { bdl = dl; bjl = j; }
            if (dh < bdh) { bdh = dh; bjh = j; }
        }
        redD[rlo * 8 + 4 + cg] = bdl; redJ[rlo * 8 + 4 + cg] = bjl;
        redD[rhi * 8 + 4 + cg] = bdh; redJ[rhi * 8 + 4 + cg] = bjh;
    }
    __syncthreads();
    if (t < 128) {
        float bd = redD[t * 8];
        int   bj = redJ[t * 8];
        #pragma unroll
        for (int w = 1; w < 8; w++) {
            float d = redD[t * 8 + w]; int j = redJ[t * 8 + w];
            if (d < bd || (d == bd && j < bj)) { bd = d; bj = j; }
        }
        int n = n0 + t;
        g_pd[(size_t)n * 32 + bn] = bd;
        g_pj[(size_t)n * 32 + bn] = bj;
    }
}

// ---------------------------------------------------------------- reduce 32 tile-partials per row
__global__ void k_finalize_argmin(float* __restrict__ out) {
    int n = blockIdx.x * 256 + threadIdx.x;
    const float* pd = g_pd + (size_t)n * 32;
    const int*   pj = g_pj + (size_t)n * 32;
    float bd = pd[0]; int bj = pj[0];
    #pragma unroll
    for (int t = 1; t < 32; t++) {
        float d = pd[t]; int j = pj[t];
        if (d < bd || (d == bd && j < bj)) { bd = d; bj = j; }
    }
    g_idx[n] = bj;
    out[OFF_IDX + n] = (float)bj;
    atomicAdd(&g_cnt[bj], 1);
}

// ---------------------------------------------------------------- one-hot rows
__global__ void k_onehot(float* __restrict__ out) {
    int row = blockIdx.x;
    int t = threadIdx.x;                  // 128 threads, 16 float2 each
    int idx = g_idx[row];
    float2* dst = (float2*)(out + OFF_OH + (size_t)row * NCODE);
    #pragma unroll
    for (int i = 0; i < 16; i++) {
        int p = t * 16 + i;
        float2 v = make_float2(0.f, 0.f);
        if ((idx >> 1) == p) ((idx & 1) ? v.y : v.x) = 1.0f;
        dst[p] = v;
    }
}

// ---------------------------------------------------------------- z_q (straight-through), z_out, loss
__global__ void k_zq_loss(const float* __restrict__ z, const float* __restrict__ E,
                          float* __restrict__ out) {
    size_t i4 = (size_t)blockIdx.x * 256 + threadIdx.x;
    size_t i = i4 * 4;
    int bb = (int)(i >> 21);
    int rem = (int)(i & 2097151u);
    int c = rem >> 13;
    int s = rem & (SPB - 1);
    float4 zp = *(const float4*)(z + i);
    int nbase = bb * SPB + s;
    float zv[4] = {zp.x, zp.y, zp.z, zp.w};
    double ls = 0.0;
    float q[4];
    #pragma unroll
    for (int u = 0; u < 4; u++) {
        int idx = g_idx[nbase + u];
        float e = E[(size_t)idx * KDIM + c];
        float d1 = __fsub_rn(e, zv[u]);
        q[u] = __fadd_rn(zv[u], d1);
        float sq = __fmul_rn(d1, d1);
        ls += (double)sq;
    }
    #pragma unroll
    for (int u = 0; u < 4; u++) {
        out[OFF_ZQ + i + u]   = q[u];
        out[OFF_ZOUT + i + u] = zv[u];
    }
    #pragma unroll
    for (int off = 16; off > 0; off >>= 1)
        ls += __shfl_down_sync(0xffffffffu, ls, off);
    __shared__ double wsum[8];
    int t = threadIdx.x;
    if ((t & 31) == 0) wsum[t >> 5] = ls;
    __syncthreads();
    if (t == 0) {
        double ssum = 0.0;
        #pragma unroll
        for (int w = 0; w < 8; w++) ssum += wsum[w];
        g_losspart[blockIdx.x] = ssum;
    }
}

// ---------------------------------------------------------------- ema update
__global__ void k_ema(const float* __restrict__ E, const float* __restrict__ ema,
                      float* __restrict__ out) {
    int i = blockIdx.x * 256 + threadIdx.x;
    float a = __fmul_rn(0.25f, ema[i]);
    float bq = __fmul_rn(0.75f, E[i]);
    out[OFF_EMA + i] = __fadd_rn(a, bq);
}

// ---------------------------------------------------------------- scalars
__global__ void k_scalars(float* __restrict__ out) {
    __shared__ double sd[256];
    int t = threadIdx.x;
    double a = 0.0;
    for (int i = t; i < 4096; i += 256) a += g_losspart[i];
    sd[t] = a;
    __syncthreads();
    for (int off = 128; off > 0; off >>= 1) {
        if (t < off) sd[t] += sd[t + off];
        __syncthreads();
    }
    if (t == 0) {
        double m = sd[0] / (double)ZTOT;
        float mf = (float)m;
        out[OFF_LOSS] = __fadd_rn(mf, __fmul_rn(0.25f, mf));
    }
    __syncthreads();
    double h = 0.0;
    for (int j = t; j < NCODE; j += 256) {
        double e = (double)g_cnt[j] / (double)NROWS;
        h += e * log(e + 1e-10);
    }
    sd[t] = h;
    __syncthreads();
    for (int off = 128; off > 0; off >>= 1) {
        if (t < off) sd[t] += sd[t + off];
        __syncthreads();
    }
    if (t == 0) out[OFF_PERP] = (float)exp(-sd[0]);
}

// ---------------------------------------------------------------- launch
extern "C" void kernel_launch(void* const* d_in, const int* in_sizes, int n_in,
                              void* d_out, int out_size) {
    const float* z   = (const float*)d_in[0];
    const float* E   = (const float*)d_in[1];
    const float* ema = (const float*)d_in[2];
    float* out = (float*)d_out;

    cudaFuncSetAttribute(k_gemm_hybrid, cudaFuncAttributeMaxDynamicSharedMemorySize, GSMEM);

    k_init<<<16, 256>>>();
    k_rownorm<<<NROWS / 256, 256>>>(z);
    k_codenorm<<<NCODE / 8, 256>>>(E);
    k_transposeE<<<dim3(NCODE / 32, KDIM / 32), dim3(32, 8)>>>(E);
    k_packA<<<2048, 256>>>(z);
    k_packB<<<1024, 256>>>(E);

    k_gemm_hybrid<<<dim3(NCODE / 128, NROWS / 128), 256, GSMEM>>>(z);

    k_finalize_argmin<<<NROWS / 256, 256>>>(out);
    k_onehot<<<NROWS, 128>>>(out);

    k_zq_loss<<<4096, 256>>>(z, E, out);
    k_ema<<<(NCODE * KDIM) / 256, 256>>>(E, ema, out);
    k_scalars<<<1, 256>>>(out);
}

// round 17
// speedup vs baseline: 1.3285x; 1.3285x over previous
#include <cuda_runtime.h>
#include <cuda_fp16.h>
#include <math.h>
#include <stdint.h>

#define NROWS 16384      // 2 * 8*32*32
#define NCODE 4096
#define KDIM  256
#define SPB   8192       // spatial per batch
#define ZTOT  4194304    // 2*256*8192

// output layout: concatenation of reference outputs, float32
#define OFF_LOSS   0ull
#define OFF_ZQ     1ull
#define OFF_PERP   4194305ull
#define OFF_OH     4194306ull
#define OFF_IDX    71303170ull
#define OFF_ZOUT   71319554ull
#define OFF_EMA    75513858ull

// B operand pre-scale: 2^12 (exact). Descale folded into epilogue FMA as 2^-11.
#define BSCALE 4096.0f

// ---------------- scratch ----------------
__device__ float  g_Anorm[NROWS];
__device__ float  g_Snorm[NCODE];
__device__ float  g_pd[NROWS * 32];
__device__ int    g_pj[NROWS * 32];
__device__ int    g_idx[NROWS];
__device__ int    g_cnt[NCODE];
__device__ double g_losspart[4096];

// fp16-split operands packed in mma.m16n8k16 fragment order (half2 per reg).
// A: [mtile 0..1023][kc16 0..15][lane 0..31][4 regs]
// B: [ntile 0..511 ][kc16 0..15][lane 0..31][2 regs]   (scaled by BSCALE)
__device__ __align__(16) uint32_t g_Afh[(size_t)1024 * 16 * 32 * 4];
__device__ __align__(16) uint32_t g_Afl[(size_t)1024 * 16 * 32 * 4];
__device__ __align__(16) uint32_t g_Bfh[(size_t)512 * 16 * 32 * 2];
__device__ __align__(16) uint32_t g_Bfl[(size_t)512 * 16 * 32 * 2];

// ---------------- helpers ----------------
__device__ __forceinline__ uint32_t smem_u32(const void* p) {
    uint32_t a;
    asm("{ .reg .u64 t; cvta.to.shared.u64 t, %1; cvt.u32.u64 %0, t; }" : "=r"(a) : "l"(p));
    return a;
}
#define CP_ASYNC16(dst, src) \
    asm volatile("cp.async.cg.shared.global [%0], [%1], 16;" :: "r"(dst), "l"(src) : "memory")
#define CP_COMMIT() asm volatile("cp.async.commit_group;" ::: "memory")
#define CP_WAIT0()  asm volatile("cp.async.wait_group 0;" ::: "memory")

__device__ __forceinline__ void mma_f16(float* c, const uint32_t* a, const uint32_t* b) {
    asm volatile("mma.sync.aligned.m16n8k16.row.col.f32.f16.f16.f32 "
        "{%0,%1,%2,%3}, {%4,%5,%6,%7}, {%8,%9}, {%0,%1,%2,%3};"
        : "+f"(c[0]), "+f"(c[1]), "+f"(c[2]), "+f"(c[3])
        : "r"(a[0]), "r"(a[1]), "r"(a[2]), "r"(a[3]), "r"(b[0]), "r"(b[1]));
}

// split one float into fp16 hi + fp16(lo) ; returns packed pair for (x,y)
__device__ __forceinline__ void split2(float x, float y, uint32_t& hi, uint32_t& lo) {
    __half hx = __float2half_rn(x), hy = __float2half_rn(y);
    float rx = __fsub_rn(x, __half2float(hx));
    float ry = __fsub_rn(y, __half2float(hy));
    __half2 h = __halves2half2(hx, hy);
    __half2 l = __halves2half2(__float2half_rn(rx), __float2half_rn(ry));
    hi = *(uint32_t*)&h;
    lo = *(uint32_t*)&l;
}

// ---------------------------------------------------------------- init
__global__ void k_init() {
    int t = blockIdx.x * 256 + threadIdx.x;
    if (t < NCODE) g_cnt[t] = 0;
}

// ---------------------------------------------------------------- row norms ||z_n||^2
__global__ void k_rownorm(const float* __restrict__ z) {
    int n = blockIdx.x * 256 + threadIdx.x;
    int b = n >> 13, s = n & (SPB - 1);
    const float* p = z + (size_t)b * (KDIM * SPB) + s;
    float a = 0.f;
    #pragma unroll 8
    for (int c = 0; c < KDIM; c++) {
        float v = p[(size_t)c * SPB];
        a = __fmaf_rn(v, v, a);
    }
    g_Anorm[n] = a;
}

// ---------------------------------------------------------------- code norms ||e_j||^2
__global__ void k_codenorm(const float* __restrict__ E) {
    int w = blockIdx.x * 8 + (threadIdx.x >> 5);
    int lane = threadIdx.x & 31;
    const float* p = E + (size_t)w * KDIM;
    float a = 0.f;
    #pragma unroll
    for (int i = 0; i < 8; i++) {
        float v = p[lane + i * 32];
        a = __fmaf_rn(v, v, a);
    }
    #pragma unroll
    for (int off = 16; off > 0; off >>= 1)
        a += __shfl_xor_sync(0xffffffffu, a, off);
    if (lane == 0) g_Snorm[w] = a;
}

// ---------------------------------------------------------------- A fragment pack
__global__ void k_packA(const float* __restrict__ z) {
    int tid = blockIdx.x * 256 + threadIdx.x;   // 524,288
    int l  = tid & 31;
    int kc = (tid >> 5) & 15;
    int T  = tid >> 9;                           // 0..1023
    int g = l >> 2, tg = l & 3;
    int m = T * 16;
    int b = m >> 13;
    int s = (m & (SPB - 1)) + g;
    int k0 = kc * 16 + tg * 2;
    const float* zb = z + ((size_t)b * KDIM * SPB);
    uint4 hi, lo;
    split2(zb[(size_t)k0 * SPB + s],           zb[(size_t)(k0 + 1) * SPB + s],     hi.x, lo.x);
    split2(zb[(size_t)k0 * SPB + s + 8],       zb[(size_t)(k0 + 1) * SPB + s + 8], hi.y, lo.y);
    split2(zb[(size_t)(k0 + 8) * SPB + s],     zb[(size_t)(k0 + 9) * SPB + s],     hi.z, lo.z);
    split2(zb[(size_t)(k0 + 8) * SPB + s + 8], zb[(size_t)(k0 + 9) * SPB + s + 8], hi.w, lo.w);
    size_t o = ((size_t)T * 16 + kc) * 128 + l * 4;
    *(uint4*)&g_Afh[o] = hi;
    *(uint4*)&g_Afl[o] = lo;
}

// ---------------------------------------------------------------- B fragment pack (scaled by BSCALE)
__global__ void k_packB(const float* __restrict__ E) {
    int tid = blockIdx.x * 256 + threadIdx.x;   // 262,144
    int l  = tid & 31;
    int kc = (tid >> 5) & 15;
    int nt = tid >> 9;                           // 0..511
    int g = l >> 2, tg = l & 3;
    int n = nt * 8 + g;
    int k0 = kc * 16 + tg * 2;
    uint32_t h0, l0, h1, l1;
    split2(E[(size_t)n * KDIM + k0] * BSCALE,     E[(size_t)n * KDIM + k0 + 1] * BSCALE, h0, l0);
    split2(E[(size_t)n * KDIM + k0 + 8] * BSCALE, E[(size_t)n * KDIM + k0 + 9] * BSCALE, h1, l1);
    size_t o = ((size_t)nt * 16 + kc) * 64 + l * 2;
    g_Bfh[o]     = h0;
    g_Bfh[o + 1] = h1;
    g_Bfl[o]     = l0;
    g_Bfl[o + 1] = l1;
}

// ---------------------------------------------------------------- mma GEMM + argmin
// block tile 128x128, stage = k32 (2 k16-chunks), double buffered, 2 CTAs/SM.
// stage layout: Ahi[2kc][8mt][32lane][16B] 8K | Alo 8K | Bhi[2kc][16nt][32lane][8B] 8K | Blo 8K
#define STG 32768
#define GSMEM (512 + 2 * STG)

__device__ __forceinline__ void copy_stage(char* sm_, int st, int ks, int bm, int bn, int t) {
    uint32_t sb = smem_u32(sm_ + 512 + st * STG);
    #pragma unroll
    for (int i = 0; i < 4; i++) {          // A: 1024 chunks of 16B
        int a = t + i * 256;
        int half = a >> 9, c = a & 511;
        int kc = c >> 8, mt = (c >> 5) & 7, lane = c & 31;
        const uint32_t* src = (half ? g_Afl : g_Afh)
            + (((size_t)(bm * 8 + mt) * 16 + ks * 2 + kc) * 32 + lane) * 4;
        CP_ASYNC16(sb + half * 8192 + c * 16, src);
    }
    #pragma unroll
    for (int i = 0; i < 4; i++) {          // B: 1024 chunks of 16B (2 lanes each)
        int a = t + i * 256;
        int half = a >> 9, c = a & 511;
        int u = c * 2;
        int kc = u >> 9, nt = (u >> 5) & 15, lane = u & 31;
        const uint32_t* src = (half ? g_Bfl : g_Bfh)
            + (((size_t)(bn * 16 + nt) * 16 + ks * 2 + kc) * 32 + lane) * 2;
        CP_ASYNC16(sb + 16384 + half * 8192 + c * 16, src);
    }
}

__global__ __launch_bounds__(256, 2)
void k_gemm_mma() {
    extern __shared__ char sm_[];
    const int t = threadIdx.x, lane = t & 31, wid = t >> 5;
    const int wm = wid >> 2;         // 0..1  (m offset wm*64)
    const int wn = wid & 3;          // 0..3  (n offset wn*32)
    const int g = lane >> 2, tg = lane & 3;
    const int bn = blockIdx.x, bm = blockIdx.y;
    const int n0 = bm * 128, j0 = bn * 128;

    float* sSn = (float*)sm_;
    if (t < 128) sSn[t] = g_Snorm[j0 + t];

    copy_stage(sm_, 0, 0, bm, bn, t);
    CP_COMMIT();

    float acc[4][4][4];
    #pragma unroll
    for (int a = 0; a < 4; a++)
        #pragma unroll
        for (int b = 0; b < 4; b++)
            #pragma unroll
            for (int c = 0; c < 4; c++) acc[a][b][c] = 0.f;

    for (int ks = 0; ks < 8; ks++) {
        CP_WAIT0();
        __syncthreads();
        if (ks + 1 < 8) {
            copy_stage(sm_, (ks + 1) & 1, ks + 1, bm, bn, t);
            CP_COMMIT();
        }
        char* sbase = sm_ + 512 + (ks & 1) * STG;
        #pragma unroll
        for (int kc = 0; kc < 2; kc++) {
            // Register-lean operand plan (for 2 CTAs/SM): keep bh+bl resident,
            // single A slot reused: ah for passes hh+hl, then al for pass lh.
            // Per-accumulator order is hh -> hl -> lh — IDENTICAL to R12 (bit-exact).
            uint32_t af[4][4], bh[4][2], bl[4][2];
            #pragma unroll
            for (int j = 0; j < 4; j++) {
                uint4 x = *(const uint4*)(sbase + ((kc * 8 + wm * 4 + j) * 32 + lane) * 16);
                af[j][0] = x.x; af[j][1] = x.y; af[j][2] = x.z; af[j][3] = x.w;
                uint2 u = *(const uint2*)(sbase + 16384 + ((kc * 16 + wn * 4 + j) * 32 + lane) * 8);
                bh[j][0] = u.x; bh[j][1] = u.y;
                uint2 v = *(const uint2*)(sbase + 24576 + ((kc * 16 + wn * 4 + j) * 32 + lane) * 8);
                bl[j][0] = v.x; bl[j][1] = v.y;
            }
            #pragma unroll
            for (int mt = 0; mt < 4; mt++)      // pass 1: hh
                #pragma unroll
                for (int nt = 0; nt < 4; nt++)
                    mma_f16(acc[mt][nt], af[mt], bh[nt]);
            #pragma unroll
            for (int mt = 0; mt < 4; mt++)      // pass 2: hl
                #pragma unroll
                for (int nt = 0; nt < 4; nt++)
                    mma_f16(acc[mt][nt], af[mt], bl[nt]);
            #pragma unroll
            for (int j = 0; j < 4; j++) {       // reload A slot with lo
                uint4 y = *(const uint4*)(sbase + 8192 + ((kc * 8 + wm * 4 + j) * 32 + lane) * 16);
                af[j][0] = y.x; af[j][1] = y.y; af[j][2] = y.z; af[j][3] = y.w;
            }
            #pragma unroll
            for (int mt = 0; mt < 4; mt++)      // pass 3: lh
                #pragma unroll
                for (int nt = 0; nt < 4; nt++)
                    mma_f16(acc[mt][nt], af[mt], bh[nt]);
        }
    }
    __syncthreads();   // stage smem free; reuse for reduction

    float* redD = (float*)(sm_ + 512);
    int*   redJ = (int*)(sm_ + 512 + 2048);

    // d = fl( fl(An+Sj) - 2 * (acc * 2^-12) ) ; descale folded: fmaf(-2^-11, acc, t) (exact)
    #pragma unroll
    for (int mt = 0; mt < 4; mt++) {
        int r0 = wm * 64 + mt * 16 + g;
        int r1 = r0 + 8;
        float an0 = g_Anorm[n0 + r0];
        float an1 = g_Anorm[n0 + r1];
        float bd0 = __int_as_float(0x7f800000), bd1 = bd0;
        int bj0 = 0, bj1 = 0;
        #pragma unroll
        for (int nt = 0; nt < 4; nt++) {
            #pragma unroll
            for (int e = 0; e < 2; e++) {
                int cl = wn * 32 + nt * 8 + tg * 2 + e;
                float sj = sSn[cl];
                int j = j0 + cl;
                float d0 = __fmaf_rn(-0x1p-11f, acc[mt][nt][e],     __fadd_rn(an0, sj));
                float d1 = __fmaf_rn(-0x1p-11f, acc[mt][nt][2 + e], __fadd_rn(an1, sj));
                if (d0 < bd0) { bd0 = d0; bj0 = j; }
                if (d1 < bd1) { bd1 = d1; bj1 = j; }
            }
        }
        #pragma unroll
        for (int off = 1; off <= 2; off <<= 1) {
            float d2 = __shfl_xor_sync(0xffffffffu, bd0, off);
            int   j2 = __shfl_xor_sync(0xffffffffu, bj0, off);
            if (d2 < bd0 || (d2 == bd0 && j2 < bj0)) { bd0 = d2; bj0 = j2; }
            float d3 = __shfl_xor_sync(0xffffffffu, bd1, off);
            int   j3 = __shfl_xor_sync(0xffffffffu, bj1, off);
            if (d3 < bd1 || (d3 == bd1 && j3 < bj1)) { bd1 = d3; bj1 = j3; }
        }
        if (tg == 0) {
            redD[r0 * 4 + wn] = bd0; redJ[r0 * 4 + wn] = bj0;
            redD[r1 * 4 + wn] = bd1; redJ[r1 * 4 + wn] = bj1;
        }
    }
    __syncthreads();
    if (t < 128) {
        float bd = redD[t * 4];
        int   bj = redJ[t * 4];
        #pragma unroll
        for (int w = 1; w < 4; w++) {
            float d = redD[t * 4 + w]; int j = redJ[t * 4 + w];
            if (d < bd || (d == bd && j < bj)) { bd = d; bj = j; }
        }
        int n = n0 + t;
        g_pd[(size_t)n * 32 + bn] = bd;
        g_pj[(size_t)n * 32 + bn] = bj;
    }
}

// ---------------------------------------------------------------- reduce 32 tile-partials per row
__global__ void k_finalize_argmin(float* __restrict__ out) {
    int n = blockIdx.x * 256 + threadIdx.x;
    const float* pd = g_pd + (size_t)n * 32;
    const int*   pj = g_pj + (size_t)n * 32;
    float bd = pd[0]; int bj = pj[0];
    #pragma unroll
    for (int t = 1; t < 32; t++) {
        float d = pd[t]; int j = pj[t];
        if (d < bd || (d == bd && j < bj)) { bd = d; bj = j; }
    }
    g_idx[n] = bj;
    out[OFF_IDX + n] = (float)bj;
    atomicAdd(&g_cnt[bj], 1);
}

// ---------------------------------------------------------------- one-hot rows (zeros + the 1), float2 stores
__global__ void k_onehot(float* __restrict__ out) {
    int row = blockIdx.x;
    int t = threadIdx.x;                  // 128 threads, 16 float2 each
    int idx = g_idx[row];
    float2* dst = (float2*)(out + OFF_OH + (size_t)row * NCODE);
    #pragma unroll
    for (int i = 0; i < 16; i++) {
        int p = t * 16 + i;               // float2 slot 0..2047
        float2 v = make_float2(0.f, 0.f);
        if ((idx >> 1) == p) ((idx & 1) ? v.y : v.x) = 1.0f;
        dst[p] = v;
    }
}

// ---------------------------------------------------------------- z_q (straight-through), z_out, loss
__global__ void k_zq_loss(const float* __restrict__ z, const float* __restrict__ E,
                          float* __restrict__ out) {
    size_t i4 = (size_t)blockIdx.x * 256 + threadIdx.x;
    size_t i = i4 * 4;
    int bb = (int)(i >> 21);
    int rem = (int)(i & 2097151u);
    int c = rem >> 13;
    int s = rem & (SPB - 1);
    float4 zp = *(const float4*)(z + i);
    int nbase = bb * SPB + s;
    float zv[4] = {zp.x, zp.y, zp.z, zp.w};
    double ls = 0.0;
    float q[4];
    #pragma unroll
    for (int u = 0; u < 4; u++) {
        int idx = g_idx[nbase + u];
        float e = E[(size_t)idx * KDIM + c];
        float d1 = __fsub_rn(e, zv[u]);
        q[u] = __fadd_rn(zv[u], d1);
        float sq = __fmul_rn(d1, d1);
        ls += (double)sq;
    }
    #pragma unroll
    for (int u = 0; u < 4; u++) {
        out[OFF_ZQ + i + u]   = q[u];
        out[OFF_ZOUT + i + u] = zv[u];
    }
    #pragma unroll
    for (int off = 16; off > 0; off >>= 1)
        ls += __shfl_down_sync(0xffffffffu, ls, off);
    __shared__ double wsum[8];
    int t = threadIdx.x;
    if ((t & 31) == 0) wsum[t >> 5] = ls;
    __syncthreads();
    if (t == 0) {
        double ssum = 0.0;
        #pragma unroll
        for (int w = 0; w < 8; w++) ssum += wsum[w];
        g_losspart[blockIdx.x] = ssum;
    }
}

// ---------------------------------------------------------------- ema update
__global__ void k_ema(const float* __restrict__ E, const float* __restrict__ ema,
                      float* __restrict__ out) {
    int i = blockIdx.x * 256 + threadIdx.x;
    float a = __fmul_rn(0.25f, ema[i]);
    float bq = __fmul_rn(0.75f, E[i]);
    out[OFF_EMA + i] = __fadd_rn(a, bq);
}

// ---------------------------------------------------------------- scalars
__global__ void k_scalars(float* __restrict__ out) {
    __shared__ double sd[256];
    int t = threadIdx.x;
    double a = 0.0;
    for (int i = t; i < 4096; i += 256) a += g_losspart[i];
    sd[t] = a;
    __syncthreads();
    for (int off = 128; off > 0; off >>= 1) {
        if (t < off) sd[t] += sd[t + off];
        __syncthreads();
    }
    if (t == 0) {
        double m = sd[0] / (double)ZTOT;
        float mf = (float)m;
        out[OFF_LOSS] = __fadd_rn(mf, __fmul_rn(0.25f, mf));
    }
    __syncthreads();
    double h = 0.0;
    for (int j = t; j < NCODE; j += 256) {
        double e = (double)g_cnt[j] / (double)NROWS;
        h += e * log(e + 1e-10);
    }
    sd[t] = h;
    __syncthreads();
    for (int off = 128; off > 0; off >>= 1) {
        if (t < off) sd[t] += sd[t + off];
        __syncthreads();
    }
    if (t == 0) out[OFF_PERP] = (float)exp(-sd[0]);
}

// ---------------------------------------------------------------- launch
extern "C" void kernel_launch(void* const* d_in, const int* in_sizes, int n_in,
                              void* d_out, int out_size) {
    const float* z   = (const float*)d_in[0];
    const float* E   = (const float*)d_in[1];
    const float* ema = (const float*)d_in[2];
    float* out = (float*)d_out;

    cudaFuncSetAttribute(k_gemm_mma, cudaFuncAttributeMaxDynamicSharedMemorySize, GSMEM);

    k_init<<<16, 256>>>();
    k_rownorm<<<NROWS / 256, 256>>>(z);
    k_codenorm<<<NCODE / 8, 256>>>(E);
    k_packA<<<2048, 256>>>(z);
    k_packB<<<1024, 256>>>(E);

    k_gemm_mma<<<dim3(NCODE / 128, NROWS / 128), 256, GSMEM>>>();

    k_finalize_argmin<<<NROWS / 256, 256>>>(out);
    k_onehot<<<NROWS, 128>>>(out);

    k_zq_loss<<<4096, 256>>>(z, E, out);
    k_ema<<<(NCODE * KDIM) / 256, 256>>>(E, ema, out);
    k_scalars<<<1, 256>>>(out);
}